// round 4
// baseline (speedup 1.0000x reference)
#include <cuda_runtime.h>
#include <math.h>

#define H 16
#define S 2048
#define D 128
#define M 4096
#define TOPK 16
#define TQ 64
#define TK 64

// Scratch (device globals; cudaMalloc is forbidden)
__device__ float g_kn[H * M * D];   // 32 MB normalized key memories
__device__ float g_qn[H * S * D];   // 16 MB normalized queries

#define FMA_F32X2(d, a, b, c) \
    asm("fma.rn.f32x2 %0, %1, %2, %3;" : "=l"(d) : "l"(a), "l"(b), "l"(c))

// ---------------------------------------------------------------------------
// Row L2-normalization matching XLA:CPU rounding exactly:
//   acc = 0; for d=0..127: acc = fadd_rn(acc, fmul_rn(x_d, x_d))   (NO fma!)
//   n = sqrt_rn(acc); dnm = max(n, 1e-6); out_d = fdiv_rn(x_d, dnm)
// Block: 256 threads, 64 rows. Rows staged in shared (pad 129 -> conflict-free
// both for the coalesced fill and the per-thread sequential row walk).
// ---------------------------------------------------------------------------
__global__ __launch_bounds__(256)
void normalize_rows(const float* __restrict__ src,
                    float* __restrict__ dst) {
    __shared__ float rows[64 * 129];
    __shared__ float rnorm[64];
    const int tid = threadIdx.x;
    const size_t base = (size_t)blockIdx.x * 64 * D;

    // coalesced load of 64 rows
#pragma unroll
    for (int i = 0; i < 32; i++) {
        int idx = i * 256 + tid;          // 0..8191
        int r = idx >> 7;                 // row
        int d = idx & 127;
        rows[r * 129 + d] = src[base + (size_t)r * D + d];
    }
    __syncthreads();

    // sequential reduction, one thread per row (threads 0..63)
    if (tid < 64) {
        const float* rp = rows + tid * 129;
        float acc = 0.f;
#pragma unroll 8
        for (int d = 0; d < D; d++)
            acc = __fadd_rn(acc, __fmul_rn(rp[d], rp[d]));
        float n = __fsqrt_rn(acc);
        rnorm[tid] = fmaxf(n, 1e-6f);
    }
    __syncthreads();

    // divide + coalesced store
#pragma unroll
    for (int i = 0; i < 32; i++) {
        int idx = i * 256 + tid;
        int r = idx >> 7;
        int d = idx & 127;
        dst[base + (size_t)r * D + d] = __fdiv_rn(rows[r * 129 + d], rnorm[r]);
    }
}

// ---------------------------------------------------------------------------
// Main fused kernel, per (head, 64-query tile):
//   phase 1: f32x2-packed sims (per-lane IEEE FMA chain over d=0..127, exactly
//            matching a sequential fp32 fma dot), per-part register top-16
//   phase 2: merge 4x16 candidates -> exact top-16 desc, lowest-index ties
//   phase 3: weighted value gather (descending order) + gated combine
// ---------------------------------------------------------------------------
__global__ __launch_bounds__(256, 2)
void praxis_main(const float* __restrict__ outputs,
                 const float* __restrict__ gate,
                 const float* __restrict__ vmem,
                 float* __restrict__ out) {
    extern __shared__ float smem[];
    float* sQ   = smem;                 // [D][TQ] 32 KB (phase 1)
    float* sK   = smem + D * TQ;        // [D][TK] 32 KB (phase 1)
    // post-loop aliases (guarded by __syncthreads):
    float* candS = smem;                              // [64][65] floats
    int*   candI = (int*)(smem + 64 * 65);            // [64][65] ints
    float* finS  = (float*)(smem + 2 * 64 * 65);      // [64][16]
    int*   finI  = (int*)(smem + 2 * 64 * 65 + TQ * TOPK);

    const int h     = blockIdx.y;
    const int qtile = blockIdx.x;
    const int tid   = threadIdx.x;
    const int q     = tid & 63;
    const int part  = tid >> 6;

    // ---- Load query tile transposed [d][q] ----
    const float4* qsrc = reinterpret_cast<const float4*>(
        g_qn + ((size_t)h * S + (size_t)qtile * TQ) * D);
#pragma unroll
    for (int i = 0; i < 8; i++) {
        int idx = i * 256 + tid;
        int r   = idx & 63;
        int c4  = idx >> 6;
        float4 v = qsrc[r * (D / 4) + c4];
        sQ[(c4 * 4 + 0) * TQ + r] = v.x;
        sQ[(c4 * 4 + 1) * TQ + r] = v.y;
        sQ[(c4 * 4 + 2) * TQ + r] = v.z;
        sQ[(c4 * 4 + 3) * TQ + r] = v.w;
    }

    // ---- Register top-16 state ----
    float ls[TOPK]; int li[TOPK];
#pragma unroll
    for (int j = 0; j < TOPK; j++) { ls[j] = -INFINITY; li[j] = 0; }
    float lmin = -INFINITY;

    const float4* ksrc = reinterpret_cast<const float4*>(g_kn + (size_t)h * M * D);

    for (int c = 0; c < M / TK; c++) {
        __syncthreads();
#pragma unroll
        for (int i = 0; i < 8; i++) {
            int idx = i * 256 + tid;
            int r   = idx & 63;
            int c4  = idx >> 6;
            float4 v = ksrc[(size_t)(c * TK + r) * (D / 4) + c4];
            sK[(c4 * 4 + 0) * TK + r] = v.x;
            sK[(c4 * 4 + 1) * TK + r] = v.y;
            sK[(c4 * 4 + 2) * TK + r] = v.z;
            sK[(c4 * 4 + 3) * TK + r] = v.w;
        }
        __syncthreads();

        const ulonglong2* sk8 = reinterpret_cast<const ulonglong2*>(sK);
        unsigned long long acc[8];
#pragma unroll
        for (int t = 0; t < 8; t++) acc[t] = 0ull;   // packed (+0.f, +0.f)

#pragma unroll 4
        for (int d = 0; d < D; d++) {
            float qv = sQ[d * TQ + q];
            unsigned long long q2;
            asm("mov.b64 %0, {%1, %1};" : "=l"(q2) : "f"(qv));
            ulonglong2 k0 = sk8[d * 16 + part * 4 + 0];
            ulonglong2 k1 = sk8[d * 16 + part * 4 + 1];
            ulonglong2 k2 = sk8[d * 16 + part * 4 + 2];
            ulonglong2 k3 = sk8[d * 16 + part * 4 + 3];
            FMA_F32X2(acc[0], q2, k0.x, acc[0]);
            FMA_F32X2(acc[1], q2, k0.y, acc[1]);
            FMA_F32X2(acc[2], q2, k1.x, acc[2]);
            FMA_F32X2(acc[3], q2, k1.y, acc[3]);
            FMA_F32X2(acc[4], q2, k2.x, acc[4]);
            FMA_F32X2(acc[5], q2, k2.y, acc[5]);
            FMA_F32X2(acc[6], q2, k3.x, acc[6]);
            FMA_F32X2(acc[7], q2, k3.y, acc[7]);
        }

        float accf[16];
#pragma unroll
        for (int t = 0; t < 8; t++)
            asm("mov.b64 {%0, %1}, %2;" : "=f"(accf[2 * t]), "=f"(accf[2 * t + 1]) : "l"(acc[t]));

        int kbase = c * TK + part * 16;
#pragma unroll
        for (int t = 0; t < 16; t++) {
            float s = accf[t];
            if (s > lmin) {
                bool done = false;
#pragma unroll
                for (int j = 0; j < TOPK; j++) {
                    if (!done && ls[j] == lmin) { ls[j] = s; li[j] = kbase + t; done = true; }
                }
                lmin = ls[0];
#pragma unroll
                for (int j = 1; j < TOPK; j++) lmin = fminf(lmin, ls[j]);
            }
        }
    }
    __syncthreads();  // retire sQ/sK reads before alias writes

    // ---- Dump per-part candidates (stride 65 -> conflict-free) ----
#pragma unroll
    for (int j = 0; j < TOPK; j++) {
        candS[q * 65 + part * 16 + j] = ls[j];
        candI[q * 65 + part * 16 + j] = li[j];
    }
    __syncthreads();

    // ---- Merge: exact top-16 of 64, descending, lowest-index tie-break ----
    if (tid < 64) {
        int qq = tid;
        for (int p = 0; p < TOPK; p++) {
            float best = -INFINITY; int bj = 0; int bi = 0x7fffffff;
            for (int j = 0; j < 64; j++) {
                float v = candS[qq * 65 + j];
                int idx = candI[qq * 65 + j];
                if (v > best || (v == best && idx < bi)) { best = v; bj = j; bi = idx; }
            }
            finS[qq * TOPK + p] = best;
            finI[qq * TOPK + p] = bi;
            candS[qq * 65 + bj] = -INFINITY;
        }
    }
    __syncthreads();

    // ---- Weighted value gather (descending order == reference) + combine ----
    {
        int oq   = tid >> 2;
        int dseg = tid & 3;
        float4 a4[8];
#pragma unroll
        for (int j = 0; j < 8; j++) a4[j] = make_float4(0.f, 0.f, 0.f, 0.f);
        const float4* vm4 = reinterpret_cast<const float4*>(vmem + (size_t)h * M * D);
        for (int n = 0; n < TOPK; n++) {
            float w  = finS[oq * TOPK + n];
            int   ki = finI[oq * TOPK + n];
            const float4* row = vm4 + (size_t)ki * (D / 4) + dseg * 8;
#pragma unroll
            for (int j = 0; j < 8; j++) {
                float4 v = row[j];
                a4[j].x = __fmaf_rn(w, v.x, a4[j].x);
                a4[j].y = __fmaf_rn(w, v.y, a4[j].y);
                a4[j].z = __fmaf_rn(w, v.z, a4[j].z);
                a4[j].w = __fmaf_rn(w, v.w, a4[j].w);
            }
        }
        float gv = gate[h];
        float g  = __fdiv_rn(1.f, __fadd_rn(1.f, expf(-gv)));
        float og = __fsub_rn(1.f, g);
        size_t obase = (((size_t)h * S + (size_t)qtile * TQ + oq) * D) + (size_t)dseg * 32;
        const float4* o4 = reinterpret_cast<const float4*>(outputs + obase);
        float4*       w4 = reinterpret_cast<float4*>(out + obase);
#pragma unroll
        for (int j = 0; j < 8; j++) {
            float4 o = o4[j];
            float4 r;
            r.x = __fadd_rn(__fmul_rn(g, a4[j].x), __fmul_rn(og, o.x));
            r.y = __fadd_rn(__fmul_rn(g, a4[j].y), __fmul_rn(og, o.y));
            r.z = __fadd_rn(__fmul_rn(g, a4[j].z), __fmul_rn(og, o.z));
            r.w = __fadd_rn(__fmul_rn(g, a4[j].w), __fmul_rn(og, o.w));
            w4[j] = r;
        }
    }
}

// ---------------------------------------------------------------------------
// inputs: 0 inputs, 1 query, 2 key, 3 value, 4 outputs, 5 gate,
//         6 key_memories, 7 value_memories
// ---------------------------------------------------------------------------
extern "C" void kernel_launch(void* const* d_in, const int* in_sizes, int n_in,
                              void* d_out, int out_size) {
    (void)in_sizes; (void)n_in; (void)out_size;
    const float* query   = (const float*)d_in[1];
    const float* outputs = (const float*)d_in[4];
    const float* gate    = (const float*)d_in[5];
    const float* kmem    = (const float*)d_in[6];
    const float* vmem    = (const float*)d_in[7];
    float* out = (float*)d_out;

    float* kn_ptr = nullptr;
    float* qn_ptr = nullptr;
    cudaGetSymbolAddress((void**)&kn_ptr, g_kn);
    cudaGetSymbolAddress((void**)&qn_ptr, g_qn);

    normalize_rows<<<(H * M) / 64, 256>>>(kmem, kn_ptr);
    normalize_rows<<<(H * S) / 64, 256>>>(query, qn_ptr);

    // smem: 2*64*65 floats (cand) overlapped with 2*D*64 phase-1 tiles + fin
    const int smem_bytes = (2 * D * TQ + 2 * TQ * TOPK) * 4;  // 73728
    static int configured = 0;
    if (!configured) {
        cudaFuncSetAttribute(praxis_main,
                             cudaFuncAttributeMaxDynamicSharedMemorySize, smem_bytes);
        configured = 1;
    }
    dim3 grid(S / TQ, H);
    praxis_main<<<grid, 256, smem_bytes>>>(outputs, gate, vmem, out);
}